// round 6
// baseline (speedup 1.0000x reference)
#include <cuda_runtime.h>
#include <cuda_bf16.h>
#include <stdint.h>
#include <math.h>

// ---------------------------------------------------------------------------
// Problem constants
// ---------------------------------------------------------------------------
#define BB 4096
#define NN 19
#define EE 342
#define ET 361
#define FF 256
#define HH 512
#define OO 256
#define MM (BB * NN)      // 77824 = 512 * 152
#define MV 152            // valid rows per CTA tile (8 graphs)
#define MP 160            // padded compute rows (10 m16 tiles)
#define NC 128            // N tile

// ---------------------------------------------------------------------------
// Scratch (device globals)
// ---------------------------------------------------------------------------
__device__ __nv_bfloat16 g_Xhi[(size_t)MM * FF];
__device__ __nv_bfloat16 g_Xlo[(size_t)MM * FF];
__device__ __nv_bfloat16 g_A0hi[(size_t)MM * HH];
__device__ __nv_bfloat16 g_A0lo[(size_t)MM * HH];
__device__ __nv_bfloat16 g_A1hi[(size_t)MM * HH];
__device__ __nv_bfloat16 g_A1lo[(size_t)MM * HH];
__device__ float         g_H  [(size_t)MM * OO];
__device__ __nv_bfloat16 g_Wh[4][HH * HH];   // transposed weight splits [N,K]
__device__ __nv_bfloat16 g_Wl[4][HH * HH];
__device__ float g_als[2][4 * MM];           // logit slices, ping-pong
__device__ float g_ald[2][4 * MM];
__device__ float g_wvec[8][HH];              // ws1,wd1,ws2,wd2,ws3,wd3,ws4,wd4

// ---------------------------------------------------------------------------
// Helpers
// ---------------------------------------------------------------------------
__device__ __forceinline__ uint32_t smem_u32(const void* p) {
    uint32_t a;
    asm("{ .reg .u64 t; cvta.to.shared.u64 t, %1; cvt.u32.u64 %0, t; }"
        : "=r"(a) : "l"(p));
    return a;
}
#define SWZ(o) ((o) ^ (((o) >> 3) & 0x70))

__device__ __forceinline__ void cp16(uint32_t s, const void* g) {
    asm volatile("cp.async.cg.shared.global [%0], [%1], 16;" :: "r"(s), "l"(g));
}

__device__ __forceinline__ void atomicMaxF(float* addr, float v) {
    int* ai = (int*)addr;
    int old = __float_as_int(*addr);
    while (__int_as_float(old) < v) {
        int prev = atomicCAS(ai, old, __float_as_int(v));
        if (prev == old) break;
        old = prev;
    }
}

// ---------------------------------------------------------------------------
// Setup kernels
// ---------------------------------------------------------------------------
// w_s[k] = sum_c W[k,c]*a_s[c] ; w_d likewise.  warp per k-row.
__global__ void wvec_kernel(const float* __restrict__ W,
                            const float* __restrict__ a_s, const float* __restrict__ a_d,
                            int Kd, int Nd, float* __restrict__ ws, float* __restrict__ wd) {
    int wid = threadIdx.x >> 5, lane = threadIdx.x & 31;
    int k = blockIdx.x * 8 + wid;
    if (k >= Kd) return;
    const float* Wr = W + (size_t)k * Nd;
    float s = 0.f, d = 0.f;
    for (int c = lane; c < Nd; c += 32) {
        float w = Wr[c];
        s += w * a_s[c];
        d += w * a_d[c];
    }
#pragma unroll
    for (int o = 16; o; o >>= 1) {
        s += __shfl_xor_sync(0xffffffffu, s, o);
        d += __shfl_xor_sync(0xffffffffu, d, o);
    }
    if (lane == 0) { ws[k] = s; wd[k] = d; }
}

// W [K,N] fp32 -> transposed splits [N,K] bf16
__global__ void split_w_kernel(const float* __restrict__ W,
                               __nv_bfloat16* __restrict__ hi,
                               __nv_bfloat16* __restrict__ lo, int K, int N) {
    int i = blockIdx.x * 256 + threadIdx.x;
    if (i < K * N) {
        int n = i / K, k = i % K;
        float v = W[(size_t)k * N + n];
        __nv_bfloat16 h = __float2bfloat16(v);
        hi[i] = h;
        lo[i] = __float2bfloat16(v - __bfloat162float(h));
    }
}

// split x to bf16 hi/lo AND compute layer-1 logits als = x.ws1, ald = x.wd1.
// warp per row (256 cols).
__global__ void __launch_bounds__(256) split_x_logits(
    const float* __restrict__ x, const float* __restrict__ ws1, const float* __restrict__ wd1,
    __nv_bfloat16* __restrict__ hi, __nv_bfloat16* __restrict__ lo,
    float* __restrict__ als, float* __restrict__ ald)
{
    __shared__ float wsS[FF], wdS[FF];
    int t = threadIdx.x;
    if (t < FF) { wsS[t] = ws1[t]; wdS[t] = wd1[t]; }
    __syncthreads();
    int wid = t >> 5, lane = t & 31;
    int row = blockIdx.x * 8 + wid;
    const float* xr = x + (size_t)row * FF;
    float s = 0.f, d = 0.f;
#pragma unroll
    for (int j = 0; j < FF / 32; j++) {
        int c = lane + 32 * j;
        float v = xr[c];
        __nv_bfloat16 h = __float2bfloat16(v);
        hi[(size_t)row * FF + c] = h;
        lo[(size_t)row * FF + c] = __float2bfloat16(v - __bfloat162float(h));
        s += v * wsS[c];
        d += v * wdS[c];
    }
#pragma unroll
    for (int o = 16; o; o >>= 1) {
        s += __shfl_xor_sync(0xffffffffu, s, o);
        d += __shfl_xor_sync(0xffffffffu, d, o);
    }
    if (lane == 0) { als[row] = s; ald[row] = d; }
}

// ---------------------------------------------------------------------------
// Fused GEMM (bf16x3 interleaved) + GAT attention/aggregation epilogue.
// CTA: M=152 valid rows (8 graphs, padded to 160), N=128 cols.
// 8 warps (2M x 4N), warp tile 80x32.  K-chunks of 64, 2-stage cp.async.
// ---------------------------------------------------------------------------
#define STAGE_SZ 73728            // Ah 20480 | Al 20480 | Bh 16384 | Bl 16384
#define PERS     147456           // persistent attn region after the stages
#define OFF_ALPHA (PERS + 0)      // 8*361 fp32 = 11552
#define OFF_EBUF  (PERS + 11552)  // 11552
#define OFF_ALSR  (PERS + 23104)  // 608
#define OFF_ALDR  (PERS + 23712)
#define OFF_NMAX  (PERS + 24320)
#define OFF_NSUM  (PERS + 24928)
#define OFF_ALSP  (PERS + 25536)
#define OFF_ALDP  (PERS + 26144)
#define OFF_BIAS  (PERS + 26752)  // 512
#define OFF_WS    (PERS + 27264)
#define OFF_WD    (PERS + 27776)
#define OFF_ESRC  (PERS + 28288)  // 342 int
#define OFF_EDST  (PERS + 29656)
#define DSMEM     178688

template <int K, int NTT, int NSL, bool LAST>
__global__ void __launch_bounds__(256, 1) gemm_fused(
    const __nv_bfloat16* __restrict__ Ahi, const __nv_bfloat16* __restrict__ Alo,
    const __nv_bfloat16* __restrict__ Bhi, const __nv_bfloat16* __restrict__ Blo,
    const int* __restrict__ ei,
    const float* __restrict__ alsIn, const float* __restrict__ aldIn,
    const float* __restrict__ bias,
    const float* __restrict__ wsn, const float* __restrict__ wdn,
    float* __restrict__ alsOut, float* __restrict__ aldOut,
    __nv_bfloat16* __restrict__ Ohi, __nv_bfloat16* __restrict__ Olo,
    float* __restrict__ Hout)
{
    extern __shared__ char smem[];
    const uint32_t sb = smem_u32(smem);
    const int tid  = threadIdx.x;
    const int wid  = tid >> 5;
    const int lane = tid & 31;
    const int bm = blockIdx.y * MV;
    const int bn = blockIdx.x * NC;
    const int wm = wid >> 2;       // 0..1 : 80-row halves
    const int wn = wid & 3;        // 0..3 : 32-col quarters

    float* alphaM = (float*)(smem + OFF_ALPHA);
    float* ebuf   = (float*)(smem + OFF_EBUF);
    float* alsR   = (float*)(smem + OFF_ALSR);
    float* aldR   = (float*)(smem + OFF_ALDR);
    float* nmax   = (float*)(smem + OFF_NMAX);
    float* nsum   = (float*)(smem + OFF_NSUM);
    float* alsP   = (float*)(smem + OFF_ALSP);
    float* aldP   = (float*)(smem + OFF_ALDP);
    float* biasS  = (float*)(smem + OFF_BIAS);
    float* wsS    = (float*)(smem + OFF_WS);
    float* wdS    = (float*)(smem + OFF_WD);
    int*   esrc   = (int*)  (smem + OFF_ESRC);
    int*   edst   = (int*)  (smem + OFF_EDST);

    constexpr int NCH = K / 64;

    auto issue = [&](int ch) {
        const uint32_t st = sb + (uint32_t)(ch & 1) * STAGE_SZ;
        const int kb = ch * 64;
        const int r = tid >> 3, c = tid & 7;
#pragma unroll
        for (int i = 0; i < 5; i++) {            // A: 160 rows (hi+lo), clamped
            int rr = r + i * 32;
            int gr = bm + rr; if (gr > MM - 1) gr = MM - 1;
            size_t go = (size_t)gr * K + kb + c * 8;
            uint32_t so = SWZ((uint32_t)(rr * 128 + c * 16));
            cp16(st + so,          Ahi + go);
            cp16(st + 20480u + so, Alo + go);
        }
#pragma unroll
        for (int i = 0; i < 4; i++) {            // B: 128 rows (hi+lo)
            int rr = r + i * 32;
            size_t go = (size_t)(bn + rr) * K + kb + c * 8;
            uint32_t so = SWZ((uint32_t)(rr * 128 + c * 16));
            cp16(st + 40960u + so, Bhi + go);
            cp16(st + 57344u + so, Blo + go);
        }
    };

    float acc[5][4][4] = {};

    issue(0);
    asm volatile("cp.async.commit_group;" ::: "memory");

    // ---------------- prologue: build dense alpha for the 8 graphs ---------
    for (int j = tid; j < EE; j += 256) { esrc[j] = ei[j]; edst[j] = ei[EE + j]; }
    if (tid < MV) {
        float s = 0.f, d = 0.f;
#pragma unroll
        for (int sl = 0; sl < NSL; sl++) {
            s += alsIn[(size_t)sl * MM + bm + tid];
            d += aldIn[(size_t)sl * MM + bm + tid];
        }
        alsR[tid] = s; aldR[tid] = d;
        nmax[tid] = -1e30f; nsum[tid] = 0.f;
        alsP[tid] = 0.f;   aldP[tid] = 0.f;
    }
    if (tid < NC) {
        biasS[tid] = bias[bn + tid];
        if (!LAST) { wsS[tid] = wsn[bn + tid]; wdS[tid] = wdn[bn + tid]; }
    }
    for (int i = tid; i < 8 * ET; i += 256) alphaM[i] = 0.f;
    __syncthreads();
    for (int idx = tid; idx < 8 * ET; idx += 256) {
        int g = idx / ET, j = idx - g * ET;
        int se = (j < EE) ? esrc[j] : (j - EE);
        int de = (j < EE) ? edst[j] : (j - EE);
        float z = alsR[g * NN + se] + aldR[g * NN + de];
        float lg = (z >= 0.f) ? z : 0.2f * z;
        ebuf[idx] = lg;
        atomicMaxF(&nmax[g * NN + de], lg);
    }
    __syncthreads();
    for (int idx = tid; idx < 8 * ET; idx += 256) {
        int g = idx / ET, j = idx - g * ET;
        int de = (j < EE) ? edst[j] : (j - EE);
        float ex = __expf(ebuf[idx] - nmax[g * NN + de]);
        ebuf[idx] = ex;
        atomicAdd(&nsum[g * NN + de], ex);
    }
    __syncthreads();
    if (tid < MV) nsum[tid] = 1.f / nsum[tid];
    __syncthreads();
    for (int idx = tid; idx < 8 * ET; idx += 256) {
        int g = idx / ET, j = idx - g * ET;
        int se = (j < EE) ? esrc[j] : (j - EE);
        int de = (j < EE) ? edst[j] : (j - EE);
        atomicAdd(&alphaM[g * ET + de * NN + se], ebuf[idx] * nsum[g * NN + de]);
    }
    // (no syncthreads needed here; the mainloop's first sync covers it)

    // ---------------- mainloop ---------------------------------------------
    for (int ch = 0; ch < NCH; ch++) {
        if (ch + 1 < NCH) {
            issue(ch + 1);
            asm volatile("cp.async.commit_group;" ::: "memory");
            asm volatile("cp.async.wait_group 1;" ::: "memory");
        } else {
            asm volatile("cp.async.wait_group 0;" ::: "memory");
        }
        __syncthreads();

        const uint32_t st  = sb + (uint32_t)(ch & 1) * STAGE_SZ;
        const uint32_t sAh = st;
        const uint32_t sAl = st + 20480u;
        const uint32_t sBh = st + 40960u;
        const uint32_t sBl = st + 57344u;
#pragma unroll
        for (int kk = 0; kk < 4; kk++) {
            uint32_t bh[8], bl[8];
#pragma unroll
            for (int g = 0; g < 2; g++) {
                int n = wn * 32 + g * 16 + ((lane >> 4) * 8) + (lane & 7);
                int c = kk * 2 + ((lane >> 3) & 1);
                uint32_t so = SWZ((uint32_t)(n * 128 + c * 16));
                asm volatile(
                    "ldmatrix.sync.aligned.m8n8.x4.shared.b16 {%0,%1,%2,%3}, [%4];"
                    : "=r"(bh[g * 4 + 0]), "=r"(bh[g * 4 + 1]),
                      "=r"(bh[g * 4 + 2]), "=r"(bh[g * 4 + 3])
                    : "r"(sBh + so));
                asm volatile(
                    "ldmatrix.sync.aligned.m8n8.x4.shared.b16 {%0,%1,%2,%3}, [%4];"
                    : "=r"(bl[g * 4 + 0]), "=r"(bl[g * 4 + 1]),
                      "=r"(bl[g * 4 + 2]), "=r"(bl[g * 4 + 3])
                    : "r"(sBl + so));
            }
#pragma unroll
            for (int mt = 0; mt < 5; mt++) {
                uint32_t ah[4], al[4];
                int m = wm * 80 + mt * 16 + (lane & 15);
                int c = kk * 2 + (lane >> 4);
                uint32_t so = SWZ((uint32_t)(m * 128 + c * 16));
                asm volatile(
                    "ldmatrix.sync.aligned.m8n8.x4.shared.b16 {%0,%1,%2,%3}, [%4];"
                    : "=r"(ah[0]), "=r"(ah[1]), "=r"(ah[2]), "=r"(ah[3])
                    : "r"(sAh + so));
                asm volatile(
                    "ldmatrix.sync.aligned.m8n8.x4.shared.b16 {%0,%1,%2,%3}, [%4];"
                    : "=r"(al[0]), "=r"(al[1]), "=r"(al[2]), "=r"(al[3])
                    : "r"(sAl + so));
#pragma unroll
                for (int nt = 0; nt < 4; nt++) {
                    float* d = acc[mt][nt];
                    asm volatile(
                        "mma.sync.aligned.m16n8k16.row.col.f32.bf16.bf16.f32 "
                        "{%0,%1,%2,%3}, {%4,%5,%6,%7}, {%8,%9}, {%0,%1,%2,%3};"
                        : "+f"(d[0]), "+f"(d[1]), "+f"(d[2]), "+f"(d[3])
                        : "r"(ah[0]), "r"(ah[1]), "r"(ah[2]), "r"(ah[3]),
                          "r"(bh[nt * 2]), "r"(bh[nt * 2 + 1]));
                    asm volatile(
                        "mma.sync.aligned.m16n8k16.row.col.f32.bf16.bf16.f32 "
                        "{%0,%1,%2,%3}, {%4,%5,%6,%7}, {%8,%9}, {%0,%1,%2,%3};"
                        : "+f"(d[0]), "+f"(d[1]), "+f"(d[2]), "+f"(d[3])
                        : "r"(al[0]), "r"(al[1]), "r"(al[2]), "r"(al[3]),
                          "r"(bh[nt * 2]), "r"(bh[nt * 2 + 1]));
                    asm volatile(
                        "mma.sync.aligned.m16n8k16.row.col.f32.bf16.bf16.f32 "
                        "{%0,%1,%2,%3}, {%4,%5,%6,%7}, {%8,%9}, {%0,%1,%2,%3};"
                        : "+f"(d[0]), "+f"(d[1]), "+f"(d[2]), "+f"(d[3])
                        : "r"(ah[0]), "r"(ah[1]), "r"(ah[2]), "r"(ah[3]),
                          "r"(bl[nt * 2]), "r"(bl[nt * 2 + 1]));
                }
            }
        }
        __syncthreads();
    }

    // ---------------- epilogue ---------------------------------------------
    // 1) dump accumulators (raw h) into smem tile, stride 133 floats
    float* tile = (float*)smem;
#pragma unroll
    for (int mt = 0; mt < 5; mt++) {
        int r0 = wm * 80 + mt * 16 + (lane >> 2);
#pragma unroll
        for (int nt = 0; nt < 4; nt++) {
            int c0 = wn * 32 + nt * 8 + (lane & 3) * 2;
            float* d = acc[mt][nt];
            tile[r0 * 133 + c0]       = d[0];
            tile[r0 * 133 + c0 + 1]   = d[1];
            tile[(r0 + 8) * 133 + c0]     = d[2];
            tile[(r0 + 8) * 133 + c0 + 1] = d[3];
        }
    }
    __syncthreads();

    // 2) out = alpha * h + bias (+relu), split & store; next-layer logits
    for (int i = 0; i < (MV * NC) / 256; i++) {
        int idx = tid + (i << 8);
        int row = idx >> 7;          // all 32 lanes of a warp share this row
        int col = idx & 127;
        int g = (row * 27) >> 9;     // row / 19 for row < 152
        int n = row - g * NN;
        const float* al = &alphaM[g * ET + n * NN];
        const float* hr = &tile[(g * NN) * 133 + col];
        float a0 = biasS[col];
#pragma unroll
        for (int s2 = 0; s2 < NN; s2++) a0 += al[s2] * hr[s2 * 133];

        if (!LAST) {
            float v = fmaxf(a0, 0.f);
            __nv_bfloat16 h = __float2bfloat16(v);
            Ohi[(size_t)(bm + row) * NTT + bn + col] = h;
            Olo[(size_t)(bm + row) * NTT + bn + col] =
                __float2bfloat16(v - __bfloat162float(h));
            float ps = v * wsS[col];
            float pd = v * wdS[col];
#pragma unroll
            for (int o = 16; o; o >>= 1) {
                ps += __shfl_xor_sync(0xffffffffu, ps, o);
                pd += __shfl_xor_sync(0xffffffffu, pd, o);
            }
            if (lane == 0) {
                atomicAdd(&alsP[row], ps);
                atomicAdd(&aldP[row], pd);
            }
        } else {
            Hout[(size_t)(bm + row) * OO + bn + col] = a0;
        }
    }

    if (!LAST) {
        __syncthreads();
        if (tid < MV) {
            alsOut[(size_t)blockIdx.x * MM + bm + tid] = alsP[tid];
            aldOut[(size_t)blockIdx.x * MM + bm + tid] = aldP[tid];
        }
    }
}

// ---------------------------------------------------------------------------
// Head: scores[n] = sigmoid( h4[n] . (sum_m ws[m] h4[m]) + bs ), per graph
// ---------------------------------------------------------------------------
__global__ void __launch_bounds__(OO) head_kernel(
    const float* __restrict__ H, const float* __restrict__ ws,
    const float* __restrict__ bsc, float* __restrict__ outp)
{
    __shared__ alignas(16) float hs[NN * OO];
    __shared__ float pbuf[OO];
    const int t = threadIdx.x;
    const size_t gbase = (size_t)blockIdx.x * NN * OO;
    {
        const float4* H4 = (const float4*)(H + gbase);
        float4* hs4 = (float4*)hs;
        for (int i = t; i < NN * OO / 4; i += OO) hs4[i] = H4[i];
    }
    __syncthreads();
    {
        float pv = 0.f;
#pragma unroll
        for (int n = 0; n < NN; n++) pv += ws[n] * hs[n * OO + t];
        pbuf[t] = pv;
    }
    __syncthreads();
    {
        const int w = t >> 5, lane = t & 31, NW = OO / 32;
        const float bv = bsc[0];
        for (int n = w; n < NN; n += NW) {
            float s = 0.f;
#pragma unroll
            for (int j = 0; j < OO / 32; j++)
                s += hs[n * OO + lane + 32 * j] * pbuf[lane + 32 * j];
#pragma unroll
            for (int o = 16; o; o >>= 1)
                s += __shfl_xor_sync(0xffffffffu, s, o);
            if (lane == 0)
                outp[(size_t)blockIdx.x * NN + n] = 1.f / (1.f + __expf(-(s + bv)));
        }
    }
}

// ---------------------------------------------------------------------------
// Launch
// ---------------------------------------------------------------------------
extern "C" void kernel_launch(void* const* d_in, const int* in_sizes, int n_in,
                              void* d_out, int out_size)
{
    (void)in_sizes; (void)n_in; (void)out_size;
    const float* x   = (const float*)d_in[0];
    const int*   ei  = (const int*)  d_in[1];
    const float* W1  = (const float*)d_in[3];
    const float* as1 = (const float*)d_in[4];
    const float* ad1 = (const float*)d_in[5];
    const float* b1  = (const float*)d_in[6];
    const float* W2  = (const float*)d_in[7];
    const float* as2 = (const float*)d_in[8];
    const float* ad2 = (const float*)d_in[9];
    const float* b2  = (const float*)d_in[10];
    const float* W3  = (const float*)d_in[11];
    const float* as3 = (const float*)d_in[12];
    const float* ad3 = (const float*)d_in[13];
    const float* b3  = (const float*)d_in[14];
    const float* W4  = (const float*)d_in[15];
    const float* as4 = (const float*)d_in[16];
    const float* ad4 = (const float*)d_in[17];
    const float* b4  = (const float*)d_in[18];
    const float* ws  = (const float*)d_in[19];
    const float* bs  = (const float*)d_in[20];
    float* out = (float*)d_out;

    __nv_bfloat16 *Xhi, *Xlo, *A0hi, *A0lo, *A1hi, *A1lo, *Wh, *Wl;
    float *Hb, *alsB, *aldB, *wv;
    cudaGetSymbolAddress((void**)&Xhi,  g_Xhi);
    cudaGetSymbolAddress((void**)&Xlo,  g_Xlo);
    cudaGetSymbolAddress((void**)&A0hi, g_A0hi);
    cudaGetSymbolAddress((void**)&A0lo, g_A0lo);
    cudaGetSymbolAddress((void**)&A1hi, g_A1hi);
    cudaGetSymbolAddress((void**)&A1lo, g_A1lo);
    cudaGetSymbolAddress((void**)&Hb,   g_H);
    cudaGetSymbolAddress((void**)&Wh,   g_Wh);
    cudaGetSymbolAddress((void**)&Wl,   g_Wl);
    cudaGetSymbolAddress((void**)&alsB, g_als);
    cudaGetSymbolAddress((void**)&aldB, g_ald);
    cudaGetSymbolAddress((void**)&wv,   g_wvec);

    cudaFuncSetAttribute(gemm_fused<FF, HH, 1, false>, cudaFuncAttributeMaxDynamicSharedMemorySize, DSMEM);
    cudaFuncSetAttribute(gemm_fused<HH, HH, 4, false>, cudaFuncAttributeMaxDynamicSharedMemorySize, DSMEM);
    cudaFuncSetAttribute(gemm_fused<HH, OO, 4, true>,  cudaFuncAttributeMaxDynamicSharedMemorySize, DSMEM);

    __nv_bfloat16* Wh0 = Wh + 0 * (HH * HH);
    __nv_bfloat16* Wh1 = Wh + 1 * (HH * HH);
    __nv_bfloat16* Wh2 = Wh + 2 * (HH * HH);
    __nv_bfloat16* Wh3 = Wh + 3 * (HH * HH);
    __nv_bfloat16* Wl0 = Wl + 0 * (HH * HH);
    __nv_bfloat16* Wl1 = Wl + 1 * (HH * HH);
    __nv_bfloat16* Wl2 = Wl + 2 * (HH * HH);
    __nv_bfloat16* Wl3 = Wl + 3 * (HH * HH);

    float* ws1 = wv + 0 * HH;  float* wd1 = wv + 1 * HH;
    float* ws2 = wv + 2 * HH;  float* wd2 = wv + 3 * HH;
    float* ws3 = wv + 4 * HH;  float* wd3 = wv + 5 * HH;
    float* ws4 = wv + 6 * HH;  float* wd4 = wv + 7 * HH;

    float* als0 = alsB;             float* ald0 = aldB;
    float* als1 = alsB + 4 * MM;    float* ald1 = aldB + 4 * MM;

    // setup
    wvec_kernel<<<FF / 8, 256>>>(W1, as1, ad1, FF, HH, ws1, wd1);
    wvec_kernel<<<HH / 8, 256>>>(W2, as2, ad2, HH, HH, ws2, wd2);
    wvec_kernel<<<HH / 8, 256>>>(W3, as3, ad3, HH, HH, ws3, wd3);
    wvec_kernel<<<HH / 8, 256>>>(W4, as4, ad4, HH, OO, ws4, wd4);
    split_w_kernel<<<(FF * HH + 255) / 256, 256>>>(W1, Wh0, Wl0, FF, HH);
    split_w_kernel<<<(HH * HH + 255) / 256, 256>>>(W2, Wh1, Wl1, HH, HH);
    split_w_kernel<<<(HH * HH + 255) / 256, 256>>>(W3, Wh2, Wl2, HH, HH);
    split_w_kernel<<<(HH * OO + 255) / 256, 256>>>(W4, Wh3, Wl3, HH, OO);
    split_x_logits<<<MM / 8, 256>>>(x, ws1, wd1, Xhi, Xlo, als0, ald0);

    const dim3 gMid(HH / NC, MM / MV);   // (4, 512)
    const dim3 gLast(OO / NC, MM / MV);  // (2, 512)

    // Layer 1: reads x splits + logits slice0; writes A0 splits + logits for L2
    gemm_fused<FF, HH, 1, false><<<gMid, 256, DSMEM>>>(
        Xhi, Xlo, Wh0, Wl0, ei, als0, ald0, b1, ws2, wd2,
        als1, ald1, A0hi, A0lo, nullptr);
    // Layer 2
    gemm_fused<HH, HH, 4, false><<<gMid, 256, DSMEM>>>(
        A0hi, A0lo, Wh1, Wl1, ei, als1, ald1, b2, ws3, wd3,
        als0, ald0, A1hi, A1lo, nullptr);
    // Layer 3
    gemm_fused<HH, HH, 4, false><<<gMid, 256, DSMEM>>>(
        A1hi, A1lo, Wh2, Wl2, ei, als0, ald0, b3, ws4, wd4,
        als1, ald1, A0hi, A0lo, nullptr);
    // Layer 4 (LAST): writes aggregated h4 fp32
    gemm_fused<HH, OO, 4, true><<<gLast, 256, DSMEM>>>(
        A0hi, A0lo, Wh3, Wl3, ei, als1, ald1, b4, nullptr, nullptr,
        nullptr, nullptr, nullptr, nullptr, Hb);
    // Head
    head_kernel<<<BB, OO>>>(Hb, ws, bs, out);
}

// round 7
// speedup vs baseline: 2.0095x; 2.0095x over previous
#include <cuda_runtime.h>
#include <cuda_bf16.h>
#include <stdint.h>
#include <math.h>

// ---------------------------------------------------------------------------
// Problem constants
// ---------------------------------------------------------------------------
#define BB 4096
#define NN 19
#define EE 342
#define ET 361
#define FF 256
#define HH 512
#define OO 256
#define MM (BB * NN)      // 77824, divisible by 128

// ---------------------------------------------------------------------------
// Scratch (device globals)
// ---------------------------------------------------------------------------
__device__ __nv_bfloat16 g_Ahi[(size_t)MM * HH];
__device__ __nv_bfloat16 g_Alo[(size_t)MM * HH];
__device__ float         g_H  [(size_t)MM * HH];
__device__ __nv_bfloat16 g_Wh[4][HH * HH];   // transposed weight splits [N,K]
__device__ __nv_bfloat16 g_Wl[4][HH * HH];

// ---------------------------------------------------------------------------
// Helpers
// ---------------------------------------------------------------------------
__device__ __forceinline__ uint32_t smem_u32(const void* p) {
    uint32_t a;
    asm("{ .reg .u64 t; cvta.to.shared.u64 t, %1; cvt.u32.u64 %0, t; }"
        : "=r"(a) : "l"(p));
    return a;
}
#define SWZ(o) ((o) ^ (((o) >> 3) & 0x70))

__device__ __forceinline__ void cp16(uint32_t s, const void* g) {
    asm volatile("cp.async.cg.shared.global [%0], [%1], 16;" :: "r"(s), "l"(g));
}

// ---------------------------------------------------------------------------
// Split kernels: fp32 -> (bf16 hi, bf16 lo)
// ---------------------------------------------------------------------------
__global__ void split_x_kernel(const float* __restrict__ x,
                               __nv_bfloat16* __restrict__ hi,
                               __nv_bfloat16* __restrict__ lo, size_t n) {
    size_t i = (size_t)blockIdx.x * 256 + threadIdx.x;
    if (i < n) {
        float v = x[i];
        __nv_bfloat16 h = __float2bfloat16(v);
        hi[i] = h;
        lo[i] = __float2bfloat16(v - __bfloat162float(h));
    }
}

// W [K,N] fp32 -> transposed splits [N,K] bf16
__global__ void split_w_kernel(const float* __restrict__ W,
                               __nv_bfloat16* __restrict__ hi,
                               __nv_bfloat16* __restrict__ lo, int K, int N) {
    int i = blockIdx.x * 256 + threadIdx.x;
    if (i < K * N) {
        int n = i / K, k = i % K;
        float v = W[(size_t)k * N + n];
        __nv_bfloat16 h = __float2bfloat16(v);
        hi[i] = h;
        lo[i] = __float2bfloat16(v - __bfloat162float(h));
    }
}

// ---------------------------------------------------------------------------
// mma.sync bf16x3 GEMM, pass-interleaved, 512 threads:
//   H[M,NT] = Ah*Bh + Al*Bh + Ah*Bl  (fp32 accumulators).
// A: [M,K] bf16 row-major.  B: [NT,K] bf16 (N-major, K contiguous).
// CTA tile 128x256, 16 warps (2M x 8N), warp tile 64x32.
// K-chunks of 64 (128B rows, XOR-swizzled), 2-stage cp.async pipeline,
// stage = Ah(16K) | Al(16K) | Bh(32K) | Bl(32K) = 96KB.
// ---------------------------------------------------------------------------
#define GEMM_STAGE 98304
#define GEMM_SMEM  (2 * GEMM_STAGE)

template <int K, int NT>
__global__ void __launch_bounds__(512, 1)
gemm_mma(const __nv_bfloat16* __restrict__ Ahi, const __nv_bfloat16* __restrict__ Alo,
         const __nv_bfloat16* __restrict__ Bhi, const __nv_bfloat16* __restrict__ Blo,
         float* __restrict__ Hout)
{
    extern __shared__ char smem[];
    const uint32_t sb = smem_u32(smem);
    const int tid  = threadIdx.x;
    const int wid  = tid >> 5;
    const int lane = tid & 31;
    const int bm = blockIdx.y * 128;
    const int bn = blockIdx.x * 256;
    const int wm = wid & 1;        // 0..1  (M halves of 64)
    const int wn = wid >> 1;       // 0..7  (N groups of 32)

    constexpr int NCH = K / 64;    // K-chunks

    auto issue = [&](int ch) {
        const uint32_t st = sb + (uint32_t)(ch & 1) * GEMM_STAGE;
        const int kb = ch * 64;
        const int r = tid >> 3, c = tid & 7;   // 64 rows per i-step
#pragma unroll
        for (int i = 0; i < 2; i++) {          // A: 128 rows (hi + lo)
            int rr = r + i * 64;
            size_t go = (size_t)(bm + rr) * K + kb + c * 8;
            uint32_t so = SWZ((uint32_t)(rr * 128 + c * 16));
            cp16(st + so,          Ahi + go);
            cp16(st + 16384u + so, Alo + go);
        }
#pragma unroll
        for (int i = 0; i < 4; i++) {          // B: 256 rows (hi + lo)
            int rr = r + i * 64;
            size_t go = (size_t)(bn + rr) * K + kb + c * 8;
            uint32_t so = SWZ((uint32_t)(rr * 128 + c * 16));
            cp16(st + 32768u + so, Bhi + go);
            cp16(st + 65536u + so, Blo + go);
        }
    };

    float acc[4][4][4] = {};

    issue(0);
    asm volatile("cp.async.commit_group;" ::: "memory");

    for (int ch = 0; ch < NCH; ch++) {
        if (ch + 1 < NCH) {
            issue(ch + 1);
            asm volatile("cp.async.commit_group;" ::: "memory");
            asm volatile("cp.async.wait_group 1;" ::: "memory");
        } else {
            asm volatile("cp.async.wait_group 0;" ::: "memory");
        }
        __syncthreads();

        const uint32_t st  = sb + (uint32_t)(ch & 1) * GEMM_STAGE;
        const uint32_t sAh = st;
        const uint32_t sAl = st + 16384u;
        const uint32_t sBh = st + 32768u;
        const uint32_t sBl = st + 65536u;
#pragma unroll
        for (int kk = 0; kk < 4; kk++) {
            // B fragments (hi and lo): warp's 32 cols -> 4 n8-tiles -> 8 regs each
            uint32_t bh[8], bl[8];
#pragma unroll
            for (int g = 0; g < 2; g++) {
                int n = wn * 32 + g * 16 + ((lane >> 4) * 8) + (lane & 7);
                int c = kk * 2 + ((lane >> 3) & 1);
                uint32_t so = SWZ((uint32_t)(n * 128 + c * 16));
                asm volatile(
                    "ldmatrix.sync.aligned.m8n8.x4.shared.b16 {%0,%1,%2,%3}, [%4];"
                    : "=r"(bh[g * 4 + 0]), "=r"(bh[g * 4 + 1]),
                      "=r"(bh[g * 4 + 2]), "=r"(bh[g * 4 + 3])
                    : "r"(sBh + so));
                asm volatile(
                    "ldmatrix.sync.aligned.m8n8.x4.shared.b16 {%0,%1,%2,%3}, [%4];"
                    : "=r"(bl[g * 4 + 0]), "=r"(bl[g * 4 + 1]),
                      "=r"(bl[g * 4 + 2]), "=r"(bl[g * 4 + 3])
                    : "r"(sBl + so));
            }
#pragma unroll
            for (int mt = 0; mt < 4; mt++) {
                uint32_t ah[4], al[4];
                int m = wm * 64 + mt * 16 + (lane & 15);
                int c = kk * 2 + (lane >> 4);
                uint32_t so = SWZ((uint32_t)(m * 128 + c * 16));
                asm volatile(
                    "ldmatrix.sync.aligned.m8n8.x4.shared.b16 {%0,%1,%2,%3}, [%4];"
                    : "=r"(ah[0]), "=r"(ah[1]), "=r"(ah[2]), "=r"(ah[3])
                    : "r"(sAh + so));
                asm volatile(
                    "ldmatrix.sync.aligned.m8n8.x4.shared.b16 {%0,%1,%2,%3}, [%4];"
                    : "=r"(al[0]), "=r"(al[1]), "=r"(al[2]), "=r"(al[3])
                    : "r"(sAl + so));
#pragma unroll
                for (int nt = 0; nt < 4; nt++) {
                    float* d = acc[mt][nt];
                    asm volatile(
                        "mma.sync.aligned.m16n8k16.row.col.f32.bf16.bf16.f32 "
                        "{%0,%1,%2,%3}, {%4,%5,%6,%7}, {%8,%9}, {%0,%1,%2,%3};"
                        : "+f"(d[0]), "+f"(d[1]), "+f"(d[2]), "+f"(d[3])
                        : "r"(ah[0]), "r"(ah[1]), "r"(ah[2]), "r"(ah[3]),
                          "r"(bh[nt * 2]), "r"(bh[nt * 2 + 1]));
                    asm volatile(
                        "mma.sync.aligned.m16n8k16.row.col.f32.bf16.bf16.f32 "
                        "{%0,%1,%2,%3}, {%4,%5,%6,%7}, {%8,%9}, {%0,%1,%2,%3};"
                        : "+f"(d[0]), "+f"(d[1]), "+f"(d[2]), "+f"(d[3])
                        : "r"(al[0]), "r"(al[1]), "r"(al[2]), "r"(al[3]),
                          "r"(bh[nt * 2]), "r"(bh[nt * 2 + 1]));
                    asm volatile(
                        "mma.sync.aligned.m16n8k16.row.col.f32.bf16.bf16.f32 "
                        "{%0,%1,%2,%3}, {%4,%5,%6,%7}, {%8,%9}, {%0,%1,%2,%3};"
                        : "+f"(d[0]), "+f"(d[1]), "+f"(d[2]), "+f"(d[3])
                        : "r"(ah[0]), "r"(ah[1]), "r"(ah[2]), "r"(ah[3]),
                          "r"(bl[nt * 2]), "r"(bl[nt * 2 + 1]));
                }
            }
        }
        __syncthreads();
    }

    // Epilogue: fp32 stores.
#pragma unroll
    for (int mt = 0; mt < 4; mt++) {
        int row0 = bm + wm * 64 + mt * 16 + (lane >> 2);
#pragma unroll
        for (int nt = 0; nt < 4; nt++) {
            int col = bn + wn * 32 + nt * 8 + (lane & 3) * 2;
            *(float2*)(Hout + (size_t)row0 * NT + col) =
                make_float2(acc[mt][nt][0], acc[mt][nt][1]);
            *(float2*)(Hout + (size_t)(row0 + 8) * NT + col) =
                make_float2(acc[mt][nt][2], acc[mt][nt][3]);
        }
    }
}

// ---------------------------------------------------------------------------
// Attention + aggregation, dense-alpha. One CTA per graph, C threads.
// Softmax computed without max-subtraction (logits are O(few); exp safe;
// alpha = exp(e)/sum exp(e) is mathematically identical).
// ---------------------------------------------------------------------------
template <int C>
__device__ __forceinline__ void attn_alpha(
    const float* __restrict__ hs, const int* __restrict__ ei,
    const float* __restrict__ a_s, const float* __restrict__ a_d,
    float* als, float* ald, float* nsum, float* alphaM, int t)
{
    // per-node logits
    {
        const int w = t >> 5, lane = t & 31, NW = C / 32;
        for (int n = w; n < NN; n += NW) {
            float s = 0.f, d = 0.f;
#pragma unroll
            for (int j = 0; j < C / 32; j++) {
                float h = hs[n * C + lane + 32 * j];
                s += h * __ldg(a_s + lane + 32 * j);
                d += h * __ldg(a_d + lane + 32 * j);
            }
#pragma unroll
            for (int o = 16; o; o >>= 1) {
                s += __shfl_xor_sync(0xffffffffu, s, o);
                d += __shfl_xor_sync(0xffffffffu, d, o);
            }
            if (lane == 0) { als[n] = s; ald[n] = d; }
        }
    }
    __syncthreads();
    // edge exp + segment sum (smem cache of exp in alphaM scratch order not
    // needed; recompute is cheap)
    for (int e = t; e < ET; e += C) {
        int se = (e < EE) ? ei[e] : (e - EE);
        int de = (e < EE) ? ei[EE + e] : (e - EE);
        float z = als[se] + ald[de];
        float lg = (z >= 0.f) ? z : 0.2f * z;
        atomicAdd(&nsum[de], __expf(lg));
    }
    __syncthreads();
    if (t < NN) nsum[t] = 1.f / nsum[t];
    __syncthreads();
    for (int e = t; e < ET; e += C) {
        int se = (e < EE) ? ei[e] : (e - EE);
        int de = (e < EE) ? ei[EE + e] : (e - EE);
        float z = als[se] + ald[de];
        float lg = (z >= 0.f) ? z : 0.2f * z;
        atomicAdd(&alphaM[de * NN + se], __expf(lg) * nsum[de]);
    }
    __syncthreads();
}

template <int C, bool RELU>
__global__ void __launch_bounds__(C) gat_agg_bf(
    const float* __restrict__ H, const int* __restrict__ ei,
    const float* __restrict__ a_s, const float* __restrict__ a_d,
    const float* __restrict__ bias,
    __nv_bfloat16* __restrict__ Ohi, __nv_bfloat16* __restrict__ Olo)
{
    __shared__ alignas(16) float hs[NN * C];
    __shared__ float als[NN], ald[NN], nsum[NN];
    __shared__ float alphaM[NN * NN];

    const int t = threadIdx.x;
    const size_t gbase = (size_t)blockIdx.x * NN * C;

    if (t < NN) nsum[t] = 0.f;
    for (int i = t; i < NN * NN; i += C) alphaM[i] = 0.f;
    {
        const float4* H4 = (const float4*)(H + gbase);
        float4* hs4 = (float4*)hs;
        for (int i = t; i < NN * C / 4; i += C) hs4[i] = H4[i];
    }
    __syncthreads();

    attn_alpha<C>(hs, ei, a_s, a_d, als, ald, nsum, alphaM, t);

    float hreg[NN];
#pragma unroll
    for (int s = 0; s < NN; s++) hreg[s] = hs[s * C + t];
    const float bc = bias[t];
#pragma unroll
    for (int n = 0; n < NN; n++) {
        float acc = 0.f;
#pragma unroll
        for (int s = 0; s < NN; s++) acc += alphaM[n * NN + s] * hreg[s];
        float v = acc + bc;
        if (RELU) v = fmaxf(v, 0.f);
        __nv_bfloat16 hi = __float2bfloat16(v);
        Ohi[gbase + (size_t)n * C + t] = hi;
        Olo[gbase + (size_t)n * C + t] = __float2bfloat16(v - __bfloat162float(hi));
    }
}

// Final layer: aggregation (no relu) + fused head
__global__ void __launch_bounds__(OO) gat_final(
    const float* __restrict__ H, const int* __restrict__ ei,
    const float* __restrict__ a_s, const float* __restrict__ a_d,
    const float* __restrict__ bias, float* __restrict__ outp,
    const float* __restrict__ ws, const float* __restrict__ bsc)
{
    constexpr int C = OO;
    __shared__ alignas(16) float hs[NN * C];
    __shared__ float als[NN], ald[NN], nsum[NN];
    __shared__ float alphaM[NN * NN];
    __shared__ alignas(16) float outbuf[NN * C];
    __shared__ float pbuf[C];

    const int t = threadIdx.x;
    const size_t gbase = (size_t)blockIdx.x * NN * C;

    if (t < NN) nsum[t] = 0.f;
    for (int i = t; i < NN * NN; i += C) alphaM[i] = 0.f;
    {
        const float4* H4 = (const float4*)(H + gbase);
        float4* hs4 = (float4*)hs;
        for (int i = t; i < NN * C / 4; i += C) hs4[i] = H4[i];
    }
    __syncthreads();

    attn_alpha<C>(hs, ei, a_s, a_d, als, ald, nsum, alphaM, t);

    float hreg[NN];
#pragma unroll
    for (int s = 0; s < NN; s++) hreg[s] = hs[s * C + t];
    const float bc = bias[t];
#pragma unroll
    for (int n = 0; n < NN; n++) {
        float acc = 0.f;
#pragma unroll
        for (int s = 0; s < NN; s++) acc += alphaM[n * NN + s] * hreg[s];
        outbuf[n * C + t] = acc + bc;
    }
    __syncthreads();

    {
        float pv = 0.f;
#pragma unroll
        for (int n = 0; n < NN; n++) pv += ws[n] * outbuf[n * C + t];
        pbuf[t] = pv;
    }
    __syncthreads();
    {
        const int w = t >> 5, lane = t & 31, NW = C / 32;
        const float bv = bsc[0];
        for (int n = w; n < NN; n += NW) {
            float s = 0.f;
#pragma unroll
            for (int j = 0; j < C / 32; j++)
                s += outbuf[n * C + lane + 32 * j] * pbuf[lane + 32 * j];
#pragma unroll
            for (int o = 16; o; o >>= 1)
                s += __shfl_xor_sync(0xffffffffu, s, o);
            if (lane == 0)
                outp[(size_t)blockIdx.x * NN + n] = 1.f / (1.f + __expf(-(s + bv)));
        }
    }
}

// ---------------------------------------------------------------------------
// Launch
// ---------------------------------------------------------------------------
extern "C" void kernel_launch(void* const* d_in, const int* in_sizes, int n_in,
                              void* d_out, int out_size)
{
    (void)in_sizes; (void)n_in; (void)out_size;
    const float* x   = (const float*)d_in[0];
    const int*   ei  = (const int*)  d_in[1];
    const float* W1  = (const float*)d_in[3];
    const float* as1 = (const float*)d_in[4];
    const float* ad1 = (const float*)d_in[5];
    const float* b1  = (const float*)d_in[6];
    const float* W2  = (const float*)d_in[7];
    const float* as2 = (const float*)d_in[8];
    const float* ad2 = (const float*)d_in[9];
    const float* b2  = (const float*)d_in[10];
    const float* W3  = (const float*)d_in[11];
    const float* as3 = (const float*)d_in[12];
    const float* ad3 = (const float*)d_in[13];
    const float* b3  = (const float*)d_in[14];
    const float* W4  = (const float*)d_in[15];
    const float* as4 = (const float*)d_in[16];
    const float* ad4 = (const float*)d_in[17];
    const float* b4  = (const float*)d_in[18];
    const float* ws  = (const float*)d_in[19];
    const float* bs  = (const float*)d_in[20];
    float* out = (float*)d_out;

    __nv_bfloat16 *Ahi, *Alo, *Wh, *Wl;
    float* Hb;
    cudaGetSymbolAddress((void**)&Ahi, g_Ahi);
    cudaGetSymbolAddress((void**)&Alo, g_Alo);
    cudaGetSymbolAddress((void**)&Hb,  g_H);
    cudaGetSymbolAddress((void**)&Wh,  g_Wh);
    cudaGetSymbolAddress((void**)&Wl,  g_Wl);

    cudaFuncSetAttribute(gemm_mma<FF, HH>, cudaFuncAttributeMaxDynamicSharedMemorySize, GEMM_SMEM);
    cudaFuncSetAttribute(gemm_mma<HH, HH>, cudaFuncAttributeMaxDynamicSharedMemorySize, GEMM_SMEM);
    cudaFuncSetAttribute(gemm_mma<HH, OO>, cudaFuncAttributeMaxDynamicSharedMemorySize, GEMM_SMEM);

    __nv_bfloat16* Wh0 = Wh + 0 * (HH * HH);
    __nv_bfloat16* Wh1 = Wh + 1 * (HH * HH);
    __nv_bfloat16* Wh2 = Wh + 2 * (HH * HH);
    __nv_bfloat16* Wh3 = Wh + 3 * (HH * HH);
    __nv_bfloat16* Wl0 = Wl + 0 * (HH * HH);
    __nv_bfloat16* Wl1 = Wl + 1 * (HH * HH);
    __nv_bfloat16* Wl2 = Wl + 2 * (HH * HH);
    __nv_bfloat16* Wl3 = Wl + 3 * (HH * HH);

    split_x_kernel<<<(MM * FF + 255) / 256, 256>>>(x, Ahi, Alo, (size_t)MM * FF);
    split_w_kernel<<<(FF * HH + 255) / 256, 256>>>(W1, Wh0, Wl0, FF, HH);
    split_w_kernel<<<(HH * HH + 255) / 256, 256>>>(W2, Wh1, Wl1, HH, HH);
    split_w_kernel<<<(HH * HH + 255) / 256, 256>>>(W3, Wh2, Wl2, HH, HH);
    split_w_kernel<<<(HH * OO + 255) / 256, 256>>>(W4, Wh3, Wl3, HH, OO);

    const dim3 g2(HH / 256, MM / 128);   // (2, 608)
    const dim3 g1(OO / 256, MM / 128);   // (1, 608)

    // Layer 1
    gemm_mma<FF, HH><<<g2, 512, GEMM_SMEM>>>(Ahi, Alo, Wh0, Wl0, Hb);
    gat_agg_bf<HH, true><<<BB, HH>>>(Hb, ei, as1, ad1, b1, Ahi, Alo);
    // Layer 2
    gemm_mma<HH, HH><<<g2, 512, GEMM_SMEM>>>(Ahi, Alo, Wh1, Wl1, Hb);
    gat_agg_bf<HH, true><<<BB, HH>>>(Hb, ei, as2, ad2, b2, Ahi, Alo);
    // Layer 3
    gemm_mma<HH, HH><<<g2, 512, GEMM_SMEM>>>(Ahi, Alo, Wh2, Wl2, Hb);
    gat_agg_bf<HH, true><<<BB, HH>>>(Hb, ei, as3, ad3, b3, Ahi, Alo);
    // Layer 4 + fused head
    gemm_mma<HH, OO><<<g1, 512, GEMM_SMEM>>>(Ahi, Alo, Wh3, Wl3, Hb);
    gat_final<<<BB, OO>>>(Hb, ei, as4, ad4, b4, out, ws, bs);
}